// round 2
// baseline (speedup 1.0000x reference)
#include <cuda_runtime.h>

// Problem constants
// B=4, H=W=256, C=192, WS=8, N_HEADS=6, HEAD_DIM=32, SHIFT=4
// windows: 32x32 per image, 64 tokens per window

#define QKV_STRIDE 50331648ull            // 4*1024*6*64*32 floats per Q/K/V plane
#define ATTN_ELEMS 50331648ull            // 4*256*256*192

// Scratch (rule-compliant: __device__ globals, no allocation)
__device__ float g_qkv[3ull * QKV_STRIDE];   // [which][win*6+head][p=64][d=32]
__device__ float g_attn[ATTN_ELEMS];         // [tok (shifted frame)][192]

// ---------------------------------------------------------------------------
// Kernel 1: QKV projection with cyclic shift fused into the A-gather.
// Grid: (4096 windows, 9 N-tiles of 64), 256 threads, 64x64 tile, 4x4/thread.
// ---------------------------------------------------------------------------
__global__ __launch_bounds__(256) void k_qkv(
    const float* __restrict__ x, const float* __restrict__ w,
    const float* __restrict__ bias)
{
    const int win = blockIdx.x;            // b*1024 + wy*32 + wx
    const int n0  = blockIdx.y * 64;
    const int b   = win >> 10;
    const int wy  = (win >> 5) & 31;
    const int wx  = win & 31;

    __shared__ float As[16][64];
    __shared__ float Bs[16][64];

    const int t  = threadIdx.x;
    const int tx = t & 15;
    const int ty = t >> 4;

    // A-load mapping: thread t loads As[kk4..kk4+3][mA]
    const int mA  = t >> 2;
    const int kk4 = (t & 3) * 4;
    const int sh  = ((wy << 3) + (mA >> 3) + 4) & 255;   // shifted source row
    const int sw  = ((wx << 3) + (mA & 7) + 4) & 255;    // shifted source col
    const float* arow = x + ((((size_t)b << 8) + sh) * 256 + sw) * 192;

    // B-load mapping
    const int kkB = t >> 4;
    const int nB  = (t & 15) * 4;

    float acc[4][4] = {};

    for (int k0 = 0; k0 < 192; k0 += 16) {
        float4 av = *reinterpret_cast<const float4*>(arow + k0 + kk4);
        As[kk4 + 0][mA] = av.x;
        As[kk4 + 1][mA] = av.y;
        As[kk4 + 2][mA] = av.z;
        As[kk4 + 3][mA] = av.w;
        *reinterpret_cast<float4*>(&Bs[kkB][nB]) =
            *reinterpret_cast<const float4*>(w + (size_t)(k0 + kkB) * 576 + n0 + nB);
        __syncthreads();
#pragma unroll
        for (int kk = 0; kk < 16; kk++) {
            const float4 a  = *reinterpret_cast<const float4*>(&As[kk][ty * 4]);
            const float4 bv = *reinterpret_cast<const float4*>(&Bs[kk][tx * 4]);
            const float ar[4] = {a.x, a.y, a.z, a.w};
            const float br[4] = {bv.x, bv.y, bv.z, bv.w};
#pragma unroll
            for (int i = 0; i < 4; i++)
#pragma unroll
                for (int j = 0; j < 4; j++)
                    acc[i][j] = fmaf(ar[i], br[j], acc[i][j]);
        }
        __syncthreads();
    }

    // Epilogue: scatter into attention layout. For fixed tx the 4 columns stay
    // inside one (which, head) (n0 % 64 == 0, tx*4 aligned) -> float4 store.
    const int n_base = n0 + tx * 4;
    const int which  = n_base / 192;
    const int r      = n_base - which * 192;
    const int head   = r >> 5;
    const int d      = r & 31;
    const float4 bv4 = *reinterpret_cast<const float4*>(bias + n_base);
    float* obase = g_qkv + (size_t)which * QKV_STRIDE +
                   ((size_t)win * 6 + head) * 2048 + d;
#pragma unroll
    for (int i = 0; i < 4; i++) {
        const int m = ty * 4 + i;
        float4 st;
        st.x = acc[i][0] + bv4.x;
        st.y = acc[i][1] + bv4.y;
        st.z = acc[i][2] + bv4.z;
        st.w = acc[i][3] + bv4.w;
        *reinterpret_cast<float4*>(obase + (size_t)m * 32) = st;
    }
}

// ---------------------------------------------------------------------------
// Kernel 2: windowed attention. Grid (4096 windows, 6 heads), 64 threads
// (one per query token). K,V in smem; bias + shift-mask computed inline.
// ---------------------------------------------------------------------------
__global__ __launch_bounds__(64) void k_attn(const float* __restrict__ rel_pos)
{
    const int win  = blockIdx.x;
    const int head = blockIdx.y;
    const int b  = win >> 10;
    const int wy = (win >> 5) & 31;
    const int wx = win & 31;
    const int p  = threadIdx.x;            // query token 0..63

    __shared__ float Ks[64][32];
    __shared__ float Vs[64][32];

    const size_t base = ((size_t)win * 6 + head) * 2048;
    const float* qb = g_qkv + base;
    const float* kb = g_qkv + QKV_STRIDE + base;
    const float* vb = g_qkv + 2 * QKV_STRIDE + base;

    float q[32];
#pragma unroll
    for (int d4 = 0; d4 < 32; d4 += 4) {
        const float4 qv = *reinterpret_cast<const float4*>(qb + p * 32 + d4);
        q[d4 + 0] = qv.x; q[d4 + 1] = qv.y; q[d4 + 2] = qv.z; q[d4 + 3] = qv.w;
        *reinterpret_cast<float4*>(&Ks[p][d4]) =
            *reinterpret_cast<const float4*>(kb + p * 32 + d4);
        *reinterpret_cast<float4*>(&Vs[p][d4]) =
            *reinterpret_cast<const float4*>(vb + p * 32 + d4);
    }
    __syncthreads();

    const int y1 = p >> 3, x1 = p & 7;
    const bool lastR = (wy == 31);
    const bool lastC = (wx == 31);

    float sc[64];
    float mx = -1e30f;
#pragma unroll 4
    for (int j = 0; j < 64; j++) {
        float s = 0.f;
#pragma unroll
        for (int d = 0; d < 32; d++) s = fmaf(q[d], Ks[j][d], s);
        s *= 0.1767766953f;                // 32^-0.5
        const int y2 = j >> 3, x2 = j & 7;
        s += rel_pos[((y1 - y2 + 7) * 15 + (x1 - x2 + 7)) * 6 + head];
        const bool bad = (lastR && ((y1 < 4) != (y2 < 4))) ||
                         (lastC && ((x1 < 4) != (x2 < 4)));
        if (bad) s = -1e30f;
        sc[j] = s;
        mx = fmaxf(mx, s);
    }
    float sum = 0.f;
#pragma unroll 4
    for (int j = 0; j < 64; j++) { sc[j] = __expf(sc[j] - mx); sum += sc[j]; }
    const float inv = 1.f / sum;

    float out[32] = {};
#pragma unroll 4
    for (int j = 0; j < 64; j++) {
        const float wgt = sc[j];
#pragma unroll
        for (int d = 0; d < 32; d++) out[d] = fmaf(wgt, Vs[j][d], out[d]);
    }

    const size_t tok = (((size_t)b << 8) + (size_t)(wy * 8 + y1)) * 256 +
                       (size_t)(wx * 8 + x1);
    float* ob = g_attn + tok * 192 + head * 32;
#pragma unroll
    for (int d4 = 0; d4 < 32; d4 += 4) {
        float4 st;
        st.x = out[d4 + 0] * inv;
        st.y = out[d4 + 1] * inv;
        st.z = out[d4 + 2] * inv;
        st.w = out[d4 + 3] * inv;
        *reinterpret_cast<float4*>(ob + d4) = st;
    }
}

// ---------------------------------------------------------------------------
// Kernel 3: output projection with un-shift fused into the output scatter.
// Grid: (4096 windows, 3 N-tiles of 64), 256 threads.
// ---------------------------------------------------------------------------
__global__ __launch_bounds__(256) void k_proj(
    const float* __restrict__ w, const float* __restrict__ bias,
    float* __restrict__ out)
{
    const int win = blockIdx.x;
    const int n0  = blockIdx.y * 64;
    const int b   = win >> 10;
    const int wy  = (win >> 5) & 31;
    const int wx  = win & 31;

    __shared__ float As[16][64];
    __shared__ float Bs[16][64];

    const int t  = threadIdx.x;
    const int tx = t & 15;
    const int ty = t >> 4;

    const int mA  = t >> 2;
    const int kk4 = (t & 3) * 4;
    const int h    = (wy << 3) + (mA >> 3);
    const int wcol = (wx << 3) + (mA & 7);
    const float* arow = g_attn + ((((size_t)b << 8) + h) * 256 + wcol) * 192;

    const int kkB = t >> 4;
    const int nB  = (t & 15) * 4;

    float acc[4][4] = {};

    for (int k0 = 0; k0 < 192; k0 += 16) {
        float4 av = *reinterpret_cast<const float4*>(arow + k0 + kk4);
        As[kk4 + 0][mA] = av.x;
        As[kk4 + 1][mA] = av.y;
        As[kk4 + 2][mA] = av.z;
        As[kk4 + 3][mA] = av.w;
        *reinterpret_cast<float4*>(&Bs[kkB][nB]) =
            *reinterpret_cast<const float4*>(w + (size_t)(k0 + kkB) * 192 + n0 + nB);
        __syncthreads();
#pragma unroll
        for (int kk = 0; kk < 16; kk++) {
            const float4 a  = *reinterpret_cast<const float4*>(&As[kk][ty * 4]);
            const float4 bv = *reinterpret_cast<const float4*>(&Bs[kk][tx * 4]);
            const float ar[4] = {a.x, a.y, a.z, a.w};
            const float br[4] = {bv.x, bv.y, bv.z, bv.w};
#pragma unroll
            for (int i = 0; i < 4; i++)
#pragma unroll
                for (int j = 0; j < 4; j++)
                    acc[i][j] = fmaf(ar[i], br[j], acc[i][j]);
        }
        __syncthreads();
    }

    const int n_base = n0 + tx * 4;
    const float4 bv4 = *reinterpret_cast<const float4*>(bias + n_base);
#pragma unroll
    for (int i = 0; i < 4; i++) {
        const int m  = ty * 4 + i;
        const int oh = ((wy << 3) + (m >> 3) + 4) & 255;   // un-shift (+4 roll)
        const int ow = ((wx << 3) + (m & 7) + 4) & 255;
        float4 st;
        st.x = acc[i][0] + bv4.x;
        st.y = acc[i][1] + bv4.y;
        st.z = acc[i][2] + bv4.z;
        st.w = acc[i][3] + bv4.w;
        *reinterpret_cast<float4*>(
            out + ((((size_t)b << 8) + oh) * 256 + ow) * 192 + n_base) = st;
    }
}

// ---------------------------------------------------------------------------
extern "C" void kernel_launch(void* const* d_in, const int* in_sizes, int n_in,
                              void* d_out, int out_size)
{
    const float* x     = (const float*)d_in[0];
    const float* w_qkv = (const float*)d_in[1];
    const float* b_qkv = (const float*)d_in[2];
    const float* w_lin = (const float*)d_in[3];
    const float* b_lin = (const float*)d_in[4];
    const float* rel   = (const float*)d_in[5];
    float* out = (float*)d_out;

    k_qkv <<<dim3(4096, 9), 256>>>(x, w_qkv, b_qkv);
    k_attn<<<dim3(4096, 6), 64 >>>(rel);
    k_proj<<<dim3(4096, 3), 256>>>(w_lin, b_lin, out);
}

// round 3
// speedup vs baseline: 1.2135x; 1.2135x over previous
#include <cuda_runtime.h>

// Problem: Swin shifted-window MSA. B=4, H=W=256, C=192, WS=8, SHIFT=4,
// N_HEADS=6, HEAD_DIM=32. 4096 windows of 64 tokens.

#define QKV_STRIDE 50331648ull            // floats per Q/K/V plane
#define ATTN_ELEMS 50331648ull
typedef unsigned long long ULL;

__device__ float g_qkv[3ull * QKV_STRIDE];   // [which][win*6+head][p=64][d=32]
__device__ float g_attn[ATTN_ELEMS];         // [win][p][c=192]

// ---- f32x2 packed helpers (sm_103a double-rate fp32) ----------------------
__device__ __forceinline__ ULL fma2(ULL a, ULL b, ULL c) {
    ULL d;
    asm("fma.rn.f32x2 %0, %1, %2, %3;" : "=l"(d) : "l"(a), "l"(b), "l"(c));
    return d;
}
__device__ __forceinline__ ULL pack2(float x, float y) {
    ULL d; asm("mov.b64 %0, {%1, %2};" : "=l"(d) : "f"(x), "f"(y)); return d;
}
__device__ __forceinline__ float lo2(ULL v) {
    float x, y; asm("mov.b64 {%0, %1}, %2;" : "=f"(x), "=f"(y) : "l"(v)); return x;
}
__device__ __forceinline__ float hi2(ULL v) {
    float x, y; asm("mov.b64 {%0, %1}, %2;" : "=f"(x), "=f"(y) : "l"(v)); return y;
}

// ---------------------------------------------------------------------------
// Kernel 1: QKV projection, shift fused into A-gather.
// Tile: M=128 (2 windows) x N=64, K=192. 256 thr, 8x4 microtile, FFMA2.
// Grid (2048, 9).
// ---------------------------------------------------------------------------
__global__ __launch_bounds__(256) void k_qkv(
    const float* __restrict__ x, const float* __restrict__ w,
    const float* __restrict__ bias)
{
    const int wp = blockIdx.x;             // window pair
    const int n0 = blockIdx.y * 64;

    __shared__ float As[16][128];
    __shared__ float Bs[16][64];

    const int t = threadIdx.x;

    // A loader: row rA = t>>1, k-half kA = (t&1)*8  (8 k-floats per thread)
    const int rA = t >> 1;
    const int kA = (t & 1) * 8;
    const int winA = wp * 2 + (rA >> 6);
    const int bA = winA >> 10, wyA = (winA >> 5) & 31, wxA = winA & 31;
    const int pA = rA & 63;
    const int sh = ((wyA << 3) + (pA >> 3) + 4) & 255;   // cyclic shift
    const int sw = ((wxA << 3) + (pA & 7) + 4) & 255;
    const float* arow = x + ((((size_t)bA << 8) + sh) * 256 + sw) * 192;

    // B loader
    const int kkB = t >> 4;
    const int nB  = (t & 15) * 4;

    // compute mapping: 16x16 thread grid, each 8 rows x 4 cols
    const int tm = t >> 4;
    const int tn = t & 15;

    ULL acc[4][4];
#pragma unroll
    for (int i = 0; i < 4; i++)
#pragma unroll
        for (int j = 0; j < 4; j++) acc[i][j] = 0ull;

    float4 ra0 = *reinterpret_cast<const float4*>(arow + kA);
    float4 ra1 = *reinterpret_cast<const float4*>(arow + kA + 4);
    float4 rb  = *reinterpret_cast<const float4*>(w + (size_t)kkB * 576 + n0 + nB);

    for (int k0 = 0; k0 < 192; k0 += 16) {
        __syncthreads();
        As[kA + 0][rA] = ra0.x; As[kA + 1][rA] = ra0.y;
        As[kA + 2][rA] = ra0.z; As[kA + 3][rA] = ra0.w;
        As[kA + 4][rA] = ra1.x; As[kA + 5][rA] = ra1.y;
        As[kA + 6][rA] = ra1.z; As[kA + 7][rA] = ra1.w;
        *reinterpret_cast<float4*>(&Bs[kkB][nB]) = rb;
        __syncthreads();
        if (k0 < 176) {
            ra0 = *reinterpret_cast<const float4*>(arow + k0 + 16 + kA);
            ra1 = *reinterpret_cast<const float4*>(arow + k0 + 16 + kA + 4);
            rb  = *reinterpret_cast<const float4*>(
                      w + (size_t)(k0 + 16 + kkB) * 576 + n0 + nB);
        }
#pragma unroll
        for (int kk = 0; kk < 16; kk++) {
            const ulonglong2* ap =
                reinterpret_cast<const ulonglong2*>(&As[kk][tm * 8]);
            const ulonglong2 av0 = ap[0];
            const ulonglong2 av1 = ap[1];
            const ULL apair[4] = {av0.x, av0.y, av1.x, av1.y};
            const float4 bf = *reinterpret_cast<const float4*>(&Bs[kk][tn * 4]);
            const ULL bd[4] = {pack2(bf.x, bf.x), pack2(bf.y, bf.y),
                               pack2(bf.z, bf.z), pack2(bf.w, bf.w)};
#pragma unroll
            for (int j = 0; j < 4; j++)
#pragma unroll
                for (int i = 0; i < 4; i++)
                    acc[i][j] = fma2(apair[i], bd[j], acc[i][j]);
        }
    }

    // Epilogue: scatter into [which][win*6+head][p][d]
    const int n_base = n0 + tn * 4;
    const int which  = n_base / 192;
    const int r      = n_base - which * 192;
    const int head   = r >> 5;
    const int d      = r & 31;
    const float4 bb  = *reinterpret_cast<const float4*>(bias + n_base);
    float* gq = g_qkv + (size_t)which * QKV_STRIDE;
#pragma unroll
    for (int i2 = 0; i2 < 4; i2++) {
#pragma unroll
        for (int hh = 0; hh < 2; hh++) {
            const int m = tm * 8 + i2 * 2 + hh;
            float4 st;
            st.x = (hh ? hi2(acc[i2][0]) : lo2(acc[i2][0])) + bb.x;
            st.y = (hh ? hi2(acc[i2][1]) : lo2(acc[i2][1])) + bb.y;
            st.z = (hh ? hi2(acc[i2][2]) : lo2(acc[i2][2])) + bb.z;
            st.w = (hh ? hi2(acc[i2][3]) : lo2(acc[i2][3])) + bb.w;
            const int win = wp * 2 + (m >> 6);
            const int p   = m & 63;
            *reinterpret_cast<float4*>(
                gq + ((size_t)win * 6 + head) * 2048 + (size_t)p * 32 + d) = st;
        }
    }
}

// ---------------------------------------------------------------------------
// Kernel 2: windowed attention, FFMA2. Grid (4096, 6), 64 threads.
// ---------------------------------------------------------------------------
__global__ __launch_bounds__(64) void k_attn(const float* __restrict__ rel_pos)
{
    const int win  = blockIdx.x;
    const int head = blockIdx.y;
    const int wy = (win >> 5) & 31;
    const int wx = win & 31;
    const int p  = threadIdx.x;

    __shared__ float Ks[64][32];
    __shared__ float Vs[64][32];

    const size_t base = ((size_t)win * 6 + head) * 2048;
    const float* qb = g_qkv + base;
    const float* kb = g_qkv + QKV_STRIDE + base;
    const float* vb = g_qkv + 2 * QKV_STRIDE + base;

    ULL q2[16];
#pragma unroll
    for (int u = 0; u < 8; u++) {
        const ulonglong2 qv =
            *reinterpret_cast<const ulonglong2*>(qb + p * 32 + u * 4);
        q2[2 * u] = qv.x; q2[2 * u + 1] = qv.y;
        *reinterpret_cast<float4*>(&Ks[p][u * 4]) =
            *reinterpret_cast<const float4*>(kb + p * 32 + u * 4);
        *reinterpret_cast<float4*>(&Vs[p][u * 4]) =
            *reinterpret_cast<const float4*>(vb + p * 32 + u * 4);
    }
    __syncthreads();

    const int y1 = p >> 3, x1 = p & 7;
    const bool lastR = (wy == 31);
    const bool lastC = (wx == 31);

    float sc[64];
    float mx = -1e30f;
#pragma unroll 4
    for (int j = 0; j < 64; j++) {
        ULL s2a = 0ull, s2b = 0ull;
        const ulonglong2* kp = reinterpret_cast<const ulonglong2*>(&Ks[j][0]);
#pragma unroll
        for (int u = 0; u < 8; u++) {
            const ulonglong2 kv = kp[u];
            s2a = fma2(q2[2 * u], kv.x, s2a);
            s2b = fma2(q2[2 * u + 1], kv.y, s2b);
        }
        float s = (lo2(s2a) + hi2(s2a)) + (lo2(s2b) + hi2(s2b));
        s *= 0.1767766953f;
        const int y2 = j >> 3, x2 = j & 7;
        s += rel_pos[((y1 - y2 + 7) * 15 + (x1 - x2 + 7)) * 6 + head];
        const bool bad = (lastR && ((y1 < 4) != (y2 < 4))) ||
                         (lastC && ((x1 < 4) != (x2 < 4)));
        if (bad) s = -1e30f;
        sc[j] = s;
        mx = fmaxf(mx, s);
    }
    float sum = 0.f;
#pragma unroll 4
    for (int j = 0; j < 64; j++) { sc[j] = __expf(sc[j] - mx); sum += sc[j]; }
    const float inv = 1.f / sum;

    ULL out2[16];
#pragma unroll
    for (int u = 0; u < 16; u++) out2[u] = 0ull;
#pragma unroll 4
    for (int j = 0; j < 64; j++) {
        const ULL wj = pack2(sc[j], sc[j]);
        const ulonglong2* vp = reinterpret_cast<const ulonglong2*>(&Vs[j][0]);
#pragma unroll
        for (int u = 0; u < 8; u++) {
            const ulonglong2 vv = vp[u];
            out2[2 * u]     = fma2(wj, vv.x, out2[2 * u]);
            out2[2 * u + 1] = fma2(wj, vv.y, out2[2 * u + 1]);
        }
    }

    float* ob = g_attn + ((size_t)win * 64 + p) * 192 + head * 32;
#pragma unroll
    for (int u = 0; u < 8; u++) {
        float4 st;
        st.x = lo2(out2[2 * u])     * inv;
        st.y = hi2(out2[2 * u])     * inv;
        st.z = lo2(out2[2 * u + 1]) * inv;
        st.w = hi2(out2[2 * u + 1]) * inv;
        *reinterpret_cast<float4*>(ob + u * 4) = st;
    }
}

// ---------------------------------------------------------------------------
// Kernel 3: output projection, un-shift fused into output scatter.
// Tile: M=128 x N=64, K=192. Grid (2048, 3).
// ---------------------------------------------------------------------------
__global__ __launch_bounds__(256) void k_proj(
    const float* __restrict__ w, const float* __restrict__ bias,
    float* __restrict__ out)
{
    const int wp = blockIdx.x;
    const int n0 = blockIdx.y * 64;

    __shared__ float As[16][128];
    __shared__ float Bs[16][64];

    const int t = threadIdx.x;

    const int rA = t >> 1;
    const int kA = (t & 1) * 8;
    const float* arow = g_attn + (size_t)(wp * 128 + rA) * 192;

    const int kkB = t >> 4;
    const int nB  = (t & 15) * 4;

    const int tm = t >> 4;
    const int tn = t & 15;

    ULL acc[4][4];
#pragma unroll
    for (int i = 0; i < 4; i++)
#pragma unroll
        for (int j = 0; j < 4; j++) acc[i][j] = 0ull;

    float4 ra0 = *reinterpret_cast<const float4*>(arow + kA);
    float4 ra1 = *reinterpret_cast<const float4*>(arow + kA + 4);
    float4 rb  = *reinterpret_cast<const float4*>(w + (size_t)kkB * 192 + n0 + nB);

    for (int k0 = 0; k0 < 192; k0 += 16) {
        __syncthreads();
        As[kA + 0][rA] = ra0.x; As[kA + 1][rA] = ra0.y;
        As[kA + 2][rA] = ra0.z; As[kA + 3][rA] = ra0.w;
        As[kA + 4][rA] = ra1.x; As[kA + 5][rA] = ra1.y;
        As[kA + 6][rA] = ra1.z; As[kA + 7][rA] = ra1.w;
        *reinterpret_cast<float4*>(&Bs[kkB][nB]) = rb;
        __syncthreads();
        if (k0 < 176) {
            ra0 = *reinterpret_cast<const float4*>(arow + k0 + 16 + kA);
            ra1 = *reinterpret_cast<const float4*>(arow + k0 + 16 + kA + 4);
            rb  = *reinterpret_cast<const float4*>(
                      w + (size_t)(k0 + 16 + kkB) * 192 + n0 + nB);
        }
#pragma unroll
        for (int kk = 0; kk < 16; kk++) {
            const ulonglong2* ap =
                reinterpret_cast<const ulonglong2*>(&As[kk][tm * 8]);
            const ulonglong2 av0 = ap[0];
            const ulonglong2 av1 = ap[1];
            const ULL apair[4] = {av0.x, av0.y, av1.x, av1.y};
            const float4 bf = *reinterpret_cast<const float4*>(&Bs[kk][tn * 4]);
            const ULL bd[4] = {pack2(bf.x, bf.x), pack2(bf.y, bf.y),
                               pack2(bf.z, bf.z), pack2(bf.w, bf.w)};
#pragma unroll
            for (int j = 0; j < 4; j++)
#pragma unroll
                for (int i = 0; i < 4; i++)
                    acc[i][j] = fma2(apair[i], bd[j], acc[i][j]);
        }
    }

    const int n_base = n0 + tn * 4;
    const float4 bb = *reinterpret_cast<const float4*>(bias + n_base);
#pragma unroll
    for (int i2 = 0; i2 < 4; i2++) {
#pragma unroll
        for (int hh = 0; hh < 2; hh++) {
            const int m = tm * 8 + i2 * 2 + hh;
            const int win = wp * 2 + (m >> 6);
            const int b   = win >> 10;
            const int wy  = (win >> 5) & 31;
            const int wx  = win & 31;
            const int p   = m & 63;
            const int oh  = ((wy << 3) + (p >> 3) + 4) & 255;  // un-shift
            const int ow  = ((wx << 3) + (p & 7) + 4) & 255;
            float4 st;
            st.x = (hh ? hi2(acc[i2][0]) : lo2(acc[i2][0])) + bb.x;
            st.y = (hh ? hi2(acc[i2][1]) : lo2(acc[i2][1])) + bb.y;
            st.z = (hh ? hi2(acc[i2][2]) : lo2(acc[i2][2])) + bb.z;
            st.w = (hh ? hi2(acc[i2][3]) : lo2(acc[i2][3])) + bb.w;
            *reinterpret_cast<float4*>(
                out + ((((size_t)b << 8) + oh) * 256 + ow) * 192 + n_base) = st;
        }
    }
}

// ---------------------------------------------------------------------------
extern "C" void kernel_launch(void* const* d_in, const int* in_sizes, int n_in,
                              void* d_out, int out_size)
{
    const float* x     = (const float*)d_in[0];
    const float* w_qkv = (const float*)d_in[1];
    const float* b_qkv = (const float*)d_in[2];
    const float* w_lin = (const float*)d_in[3];
    const float* b_lin = (const float*)d_in[4];
    const float* rel   = (const float*)d_in[5];
    float* out = (float*)d_out;

    k_qkv <<<dim3(2048, 9), 256>>>(x, w_qkv, b_qkv);
    k_attn<<<dim3(4096, 6), 64 >>>(rel);
    k_proj<<<dim3(2048, 3), 256>>>(w_lin, b_lin, out);
}

// round 7
// speedup vs baseline: 1.6011x; 1.3194x over previous
#include <cuda_runtime.h>
#include <cuda_bf16.h>
#include <cstdint>

// Swin shifted-window MSA. B=4, H=W=256, C=192, WS=8, SHIFT=4, heads=6, hd=32.
#define QKV_STRIDE 50331648ull
#define ATTN_ELEMS 50331648ull
typedef unsigned long long ULL;

__device__ float g_qkv[3ull * QKV_STRIDE];   // [which][win*6+head][p=64][d=32]
__device__ float g_attn[ATTN_ELEMS];         // [win][p][c=192]

// ---------------- f32x2 helpers (attention kernel) -------------------------
__device__ __forceinline__ ULL fma2(ULL a, ULL b, ULL c) {
    ULL d; asm("fma.rn.f32x2 %0, %1, %2, %3;" : "=l"(d) : "l"(a), "l"(b), "l"(c));
    return d;
}
__device__ __forceinline__ ULL pack2(float x, float y) {
    ULL d; asm("mov.b64 %0, {%1, %2};" : "=l"(d) : "f"(x), "f"(y)); return d;
}
__device__ __forceinline__ float lo2(ULL v) {
    float x, y; asm("mov.b64 {%0, %1}, %2;" : "=f"(x), "=f"(y) : "l"(v)); return x;
}
__device__ __forceinline__ float hi2(ULL v) {
    float x, y; asm("mov.b64 {%0, %1}, %2;" : "=f"(x), "=f"(y) : "l"(v)); return y;
}

// ---------------- mma.sync helpers -----------------------------------------
__device__ __forceinline__ uint32_t smem_u32(const void* p) {
    uint32_t a;
    asm("{ .reg .u64 t; cvta.to.shared.u64 t, %1; cvt.u32.u64 %0, t; }"
        : "=r"(a) : "l"(p));
    return a;
}

#define LDM4(r, addr) \
    asm volatile("ldmatrix.sync.aligned.m8n8.x4.shared.b16 {%0,%1,%2,%3}, [%4];" \
        : "=r"((r)[0]), "=r"((r)[1]), "=r"((r)[2]), "=r"((r)[3]) : "r"(addr))

#define MMA16816(c, a, b) \
    asm volatile("mma.sync.aligned.m16n8k16.row.col.f32.bf16.bf16.f32 " \
        "{%0,%1,%2,%3}, {%4,%5,%6,%7}, {%8,%9}, {%0,%1,%2,%3};" \
        : "+f"((c)[0]), "+f"((c)[1]), "+f"((c)[2]), "+f"((c)[3]) \
        : "r"((a)[0]), "r"((a)[1]), "r"((a)[2]), "r"((a)[3]), \
          "r"((b)[0]), "r"((b)[1]))

// SMEM: bf16, padded rows of 200 elems (400 B) -> conflict-free ldmatrix.
// A: 128 rows, hi+lo. B: 64 rows, hi+lo.
#define ROWB 400
#define SA_HI 0
#define SA_LO 51200
#define SB_HI 102400
#define SB_LO 128000
#define SMEM_SZ 153600

__device__ __forceinline__ void split_store4p(char* hi, char* lo, float4 v) {
    __nv_bfloat16 h0 = __float2bfloat16(v.x);
    __nv_bfloat16 h1 = __float2bfloat16(v.y);
    __nv_bfloat16 h2 = __float2bfloat16(v.z);
    __nv_bfloat16 h3 = __float2bfloat16(v.w);
    __nv_bfloat16 l0 = __float2bfloat16(v.x - __bfloat162float(h0));
    __nv_bfloat16 l1 = __float2bfloat16(v.y - __bfloat162float(h1));
    __nv_bfloat16 l2 = __float2bfloat16(v.z - __bfloat162float(h2));
    __nv_bfloat16 l3 = __float2bfloat16(v.w - __bfloat162float(h3));
    reinterpret_cast<__nv_bfloat162*>(hi)[0] = __nv_bfloat162(h0, h1);
    reinterpret_cast<__nv_bfloat162*>(hi)[1] = __nv_bfloat162(h2, h3);
    reinterpret_cast<__nv_bfloat162*>(lo)[0] = __nv_bfloat162(l0, l1);
    reinterpret_cast<__nv_bfloat162*>(lo)[1] = __nv_bfloat162(l2, l3);
}

// Compute D(128x64) split-bf16 from staged smem. acc[2][4][4] per warp.
__device__ __forceinline__ void gemm_body(const uint32_t sbase, int lane,
                                          int m_base, int n_base,
                                          float acc[2][4][4]) {
    // A lane address: row m_base + (lane&15), k-halfstep (lane>>4)*8 elems
    const uint32_t aoff = (uint32_t)(m_base + (lane & 15)) * ROWB +
                          (uint32_t)(lane >> 4) * 16;
    const uint32_t a_hi = sbase + SA_HI + aoff;
    const uint32_t a_lo = sbase + SA_LO + aoff;
    // B lane address: n row = n_base + (lane&7) + ((lane>>4)&1)*8,
    //                 k half = ((lane>>3)&1)*8 elems
    const uint32_t boff =
        (uint32_t)(n_base + (lane & 7) + (((lane >> 4) & 1) << 3)) * ROWB +
        (uint32_t)((lane >> 3) & 1) * 16;
    const uint32_t b_hi = sbase + SB_HI + boff;
    const uint32_t b_lo = sbase + SB_LO + boff;

#pragma unroll
    for (int ks = 0; ks < 12; ks++) {
        const uint32_t kb = ks * 32;           // 16 bf16 = 32 bytes
        uint32_t ah[2][4], al[2][4], bh[2][4], bl[2][4];
        LDM4(ah[0], a_hi + kb);
        LDM4(ah[1], a_hi + 16 * ROWB + kb);
        LDM4(al[0], a_lo + kb);
        LDM4(al[1], a_lo + 16 * ROWB + kb);
        LDM4(bh[0], b_hi + kb);                // n-atoms 0,1
        LDM4(bh[1], b_hi + 16 * ROWB + kb);    // n-atoms 2,3
        LDM4(bl[0], b_lo + kb);
        LDM4(bl[1], b_lo + 16 * ROWB + kb);
#pragma unroll
        for (int mi = 0; mi < 2; mi++) {
#pragma unroll
            for (int ni = 0; ni < 4; ni++) {
                uint32_t bfh[2] = {bh[ni >> 1][(ni & 1) * 2],
                                   bh[ni >> 1][(ni & 1) * 2 + 1]};
                uint32_t bfl[2] = {bl[ni >> 1][(ni & 1) * 2],
                                   bl[ni >> 1][(ni & 1) * 2 + 1]};
                MMA16816(acc[mi][ni], ah[mi], bfh);
                MMA16816(acc[mi][ni], al[mi], bfh);
                MMA16816(acc[mi][ni], ah[mi], bfl);
            }
        }
    }
}

// ---------------------------------------------------------------------------
// Kernel 1: QKV projection. Grid (9 nt, 2048 mt), 256 threads.
// ---------------------------------------------------------------------------
__global__ __launch_bounds__(256) void k_qkv(
    const float* __restrict__ x, const float* __restrict__ w,
    const float* __restrict__ bias)
{
    extern __shared__ char sm[];
    const uint32_t sbase = smem_u32(sm);
    const int t    = threadIdx.x;
    const int lane = t & 31;
    const int wid  = t >> 5;
    const int nt   = blockIdx.x;
    const int mt   = blockIdx.y;
    const int n0   = nt * 64;

    // --- stage A (128 tokens x 192 ch), shift fused, split hi/lo
    for (int idx4 = t; idx4 < 6144; idx4 += 256) {
        const int m  = idx4 / 48;
        const int k4 = idx4 % 48;
        const int win = mt * 2 + (m >> 6);
        const int b  = win >> 10, wy = (win >> 5) & 31, wx = win & 31;
        const int p  = m & 63;
        const int shh = ((wy << 3) + (p >> 3) + 4) & 255;
        const int sww = ((wx << 3) + (p & 7) + 4) & 255;
        const float4 v = *reinterpret_cast<const float4*>(
            x + ((((size_t)b << 8) + shh) * 256 + sww) * 192 + k4 * 4);
        const uint32_t off = (uint32_t)m * ROWB + k4 * 8;
        split_store4p(sm + SA_HI + off, sm + SA_LO + off, v);
    }
    // --- stage B = W^T (64 n x 192 k), coalesced along n
    for (int i = 0; i < 12; i++) {
        const int k = i * 16 + (t >> 4);
        const int n = (t & 15) * 4;
        const float4 v = *reinterpret_cast<const float4*>(
            w + (size_t)k * 576 + n0 + n);
        const float vv[4] = {v.x, v.y, v.z, v.w};
#pragma unroll
        for (int j = 0; j < 4; j++) {
            const __nv_bfloat16 h = __float2bfloat16(vv[j]);
            const __nv_bfloat16 l = __float2bfloat16(vv[j] - __bfloat162float(h));
            const uint32_t o = (uint32_t)(n + j) * ROWB + k * 2;
            *reinterpret_cast<__nv_bfloat16*>(sm + SB_HI + o) = h;
            *reinterpret_cast<__nv_bfloat16*>(sm + SB_LO + o) = l;
        }
    }
    __syncthreads();

    const int m_base = (wid >> 1) * 32;
    const int n_base = (wid & 1) * 32;
    float acc[2][4][4] = {};
    gemm_body(sbase, lane, m_base, n_base, acc);

    // --- epilogue: scatter into g_qkv [which][win*6+head][p][d]
    const int lane4 = lane >> 2;
    const int lane2 = (lane & 3) * 2;
#pragma unroll
    for (int mi = 0; mi < 2; mi++) {
        const int r  = m_base + mi * 16 + lane4;
        const int r2 = r + 8;
        const int win = mt * 2 + (r >> 6);
        const int p  = r & 63;
        const int p2 = r2 & 63;
#pragma unroll
        for (int ni = 0; ni < 4; ni++) {
            const int ng = n0 + n_base + ni * 8 + lane2;
            const int which = ng / 192;
            const int rr = ng - which * 192;
            const int head = rr >> 5;
            const int d = rr & 31;
            const float2 bb = *reinterpret_cast<const float2*>(bias + ng);
            float* gq = g_qkv + (size_t)which * QKV_STRIDE +
                        ((size_t)win * 6 + head) * 2048 + d;
            float2 s0 = make_float2(acc[mi][ni][0] + bb.x, acc[mi][ni][1] + bb.y);
            float2 s1 = make_float2(acc[mi][ni][2] + bb.x, acc[mi][ni][3] + bb.y);
            *reinterpret_cast<float2*>(gq + (size_t)p * 32)  = s0;
            *reinterpret_cast<float2*>(gq + (size_t)p2 * 32) = s1;
        }
    }
}

// ---------------------------------------------------------------------------
// Kernel 2: windowed attention (FFMA2). Grid (4096, 6), 64 threads.
// ---------------------------------------------------------------------------
__global__ __launch_bounds__(64) void k_attn(const float* __restrict__ rel_pos)
{
    const int win  = blockIdx.x;
    const int head = blockIdx.y;
    const int wy = (win >> 5) & 31;
    const int wx = win & 31;
    const int p  = threadIdx.x;

    __shared__ float Ks[64][32];
    __shared__ float Vs[64][32];

    const size_t base = ((size_t)win * 6 + head) * 2048;
    const float* qb = g_qkv + base;
    const float* kb = g_qkv + QKV_STRIDE + base;
    const float* vb = g_qkv + 2 * QKV_STRIDE + base;

    ULL q2[16];
#pragma unroll
    for (int u = 0; u < 8; u++) {
        const ulonglong2 qv =
            *reinterpret_cast<const ulonglong2*>(qb + p * 32 + u * 4);
        q2[2 * u] = qv.x; q2[2 * u + 1] = qv.y;
        *reinterpret_cast<float4*>(&Ks[p][u * 4]) =
            *reinterpret_cast<const float4*>(kb + p * 32 + u * 4);
        *reinterpret_cast<float4*>(&Vs[p][u * 4]) =
            *reinterpret_cast<const float4*>(vb + p * 32 + u * 4);
    }
    __syncthreads();

    const int y1 = p >> 3, x1 = p & 7;
    const bool lastR = (wy == 31);
    const bool lastC = (wx == 31);

    float sc[64];
    float mx = -1e30f;
#pragma unroll 4
    for (int j = 0; j < 64; j++) {
        ULL s2a = 0ull, s2b = 0ull;
        const ulonglong2* kp = reinterpret_cast<const ulonglong2*>(&Ks[j][0]);
#pragma unroll
        for (int u = 0; u < 8; u++) {
            const ulonglong2 kv = kp[u];
            s2a = fma2(q2[2 * u], kv.x, s2a);
            s2b = fma2(q2[2 * u + 1], kv.y, s2b);
        }
        float s = (lo2(s2a) + hi2(s2a)) + (lo2(s2b) + hi2(s2b));
        s *= 0.1767766953f;
        const int y2 = j >> 3, x2 = j & 7;
        s += rel_pos[((y1 - y2 + 7) * 15 + (x1 - x2 + 7)) * 6 + head];
        const bool bad = (lastR && ((y1 < 4) != (y2 < 4))) ||
                         (lastC && ((x1 < 4) != (x2 < 4)));
        if (bad) s = -1e30f;
        sc[j] = s;
        mx = fmaxf(mx, s);
    }
    float sum = 0.f;
#pragma unroll 4
    for (int j = 0; j < 64; j++) { sc[j] = __expf(sc[j] - mx); sum += sc[j]; }
    const float inv = 1.f / sum;

    ULL out2[16];
#pragma unroll
    for (int u = 0; u < 16; u++) out2[u] = 0ull;
#pragma unroll 4
    for (int j = 0; j < 64; j++) {
        const ULL wj = pack2(sc[j], sc[j]);
        const ulonglong2* vp = reinterpret_cast<const ulonglong2*>(&Vs[j][0]);
#pragma unroll
        for (int u = 0; u < 8; u++) {
            const ulonglong2 vv = vp[u];
            out2[2 * u]     = fma2(wj, vv.x, out2[2 * u]);
            out2[2 * u + 1] = fma2(wj, vv.y, out2[2 * u + 1]);
        }
    }

    float* ob = g_attn + ((size_t)win * 64 + p) * 192 + head * 32;
#pragma unroll
    for (int u = 0; u < 8; u++) {
        float4 st;
        st.x = lo2(out2[2 * u])     * inv;
        st.y = hi2(out2[2 * u])     * inv;
        st.z = lo2(out2[2 * u + 1]) * inv;
        st.w = hi2(out2[2 * u + 1]) * inv;
        *reinterpret_cast<float4*>(ob + u * 4) = st;
    }
}

// ---------------------------------------------------------------------------
// Kernel 3: output projection. Grid (3 nt, 2048 mt), 256 threads.
// ---------------------------------------------------------------------------
__global__ __launch_bounds__(256) void k_proj(
    const float* __restrict__ w, const float* __restrict__ bias,
    float* __restrict__ out)
{
    extern __shared__ char sm[];
    const uint32_t sbase = smem_u32(sm);
    const int t    = threadIdx.x;
    const int lane = t & 31;
    const int wid  = t >> 5;
    const int nt   = blockIdx.x;
    const int mt   = blockIdx.y;
    const int n0   = nt * 64;

    // --- stage A (contiguous 128x192 from g_attn)
    const float* abase = g_attn + (size_t)mt * 128 * 192;
    for (int idx4 = t; idx4 < 6144; idx4 += 256) {
        const int m  = idx4 / 48;
        const int k4 = idx4 % 48;
        const float4 v = *reinterpret_cast<const float4*>(abase + m * 192 + k4 * 4);
        const uint32_t off = (uint32_t)m * ROWB + k4 * 8;
        split_store4p(sm + SA_HI + off, sm + SA_LO + off, v);
    }
    // --- stage B = W^T
    for (int i = 0; i < 12; i++) {
        const int k = i * 16 + (t >> 4);
        const int n = (t & 15) * 4;
        const float4 v = *reinterpret_cast<const float4*>(
            w + (size_t)k * 192 + n0 + n);
        const float vv[4] = {v.x, v.y, v.z, v.w};
#pragma unroll
        for (int j = 0; j < 4; j++) {
            const __nv_bfloat16 h = __float2bfloat16(vv[j]);
            const __nv_bfloat16 l = __float2bfloat16(vv[j] - __bfloat162float(h));
            const uint32_t o = (uint32_t)(n + j) * ROWB + k * 2;
            *reinterpret_cast<__nv_bfloat16*>(sm + SB_HI + o) = h;
            *reinterpret_cast<__nv_bfloat16*>(sm + SB_LO + o) = l;
        }
    }
    __syncthreads();

    const int m_base = (wid >> 1) * 32;
    const int n_base = (wid & 1) * 32;
    float acc[2][4][4] = {};
    gemm_body(sbase, lane, m_base, n_base, acc);

    // --- epilogue: un-shift scatter to out
    const int lane4 = lane >> 2;
    const int lane2 = (lane & 3) * 2;
#pragma unroll
    for (int mi = 0; mi < 2; mi++) {
#pragma unroll
        for (int half = 0; half < 2; half++) {
            const int r = m_base + mi * 16 + half * 8 + lane4;
            const int win = mt * 2 + (r >> 6);
            const int b  = win >> 10;
            const int wy = (win >> 5) & 31;
            const int wx = win & 31;
            const int p  = r & 63;
            const int oh = ((wy << 3) + (p >> 3) + 4) & 255;
            const int ow = ((wx << 3) + (p & 7) + 4) & 255;
            float* orow = out + ((((size_t)b << 8) + oh) * 256 + ow) * 192;
#pragma unroll
            for (int ni = 0; ni < 4; ni++) {
                const int ng = n0 + n_base + ni * 8 + lane2;
                const float2 bb = *reinterpret_cast<const float2*>(bias + ng);
                float2 st;
                st.x = acc[mi][ni][half * 2 + 0] + bb.x;
                st.y = acc[mi][ni][half * 2 + 1] + bb.y;
                *reinterpret_cast<float2*>(orow + ng) = st;
            }
        }
    }
}

// ---------------------------------------------------------------------------
extern "C" void kernel_launch(void* const* d_in, const int* in_sizes, int n_in,
                              void* d_out, int out_size)
{
    const float* x     = (const float*)d_in[0];
    const float* w_qkv = (const float*)d_in[1];
    const float* b_qkv = (const float*)d_in[2];
    const float* w_lin = (const float*)d_in[3];
    const float* b_lin = (const float*)d_in[4];
    const float* rel   = (const float*)d_in[5];
    float* out = (float*)d_out;

    cudaFuncSetAttribute(k_qkv, cudaFuncAttributeMaxDynamicSharedMemorySize, SMEM_SZ);
    cudaFuncSetAttribute(k_proj, cudaFuncAttributeMaxDynamicSharedMemorySize, SMEM_SZ);

    k_qkv <<<dim3(9, 2048), 256, SMEM_SZ>>>(x, w_qkv, b_qkv);
    k_attn<<<dim3(4096, 6), 64>>>(rel);
    k_proj<<<dim3(3, 2048), 256, SMEM_SZ>>>(w_lin, b_lin, out);
}

// round 8
// speedup vs baseline: 2.9604x; 1.8491x over previous
#include <cuda_runtime.h>
#include <cuda_bf16.h>
#include <cstdint>

// Swin shifted-window MSA. B=4, H=W=256, C=192, WS=8, SHIFT=4, heads=6, hd=32.
#define QKV_STRIDE 50331648ull
#define ATTN_ELEMS 50331648ull
typedef unsigned long long ULL;

__device__ float g_qkv[3ull * QKV_STRIDE];   // [which][win*6+head][p=64][d=32]
__device__ float g_attn[ATTN_ELEMS];         // [win][p][c=192]

// Pre-converted weights, [n][k] bf16, hi/lo planes.
__device__ __nv_bfloat16 g_wq_hi[576 * 192];
__device__ __nv_bfloat16 g_wq_lo[576 * 192];
__device__ __nv_bfloat16 g_wl_hi[192 * 192];
__device__ __nv_bfloat16 g_wl_lo[192 * 192];

// ---------------- f32x2 helpers (attention kernel) -------------------------
__device__ __forceinline__ ULL fma2(ULL a, ULL b, ULL c) {
    ULL d; asm("fma.rn.f32x2 %0, %1, %2, %3;" : "=l"(d) : "l"(a), "l"(b), "l"(c));
    return d;
}
__device__ __forceinline__ ULL pack2(float x, float y) {
    ULL d; asm("mov.b64 %0, {%1, %2};" : "=l"(d) : "f"(x), "f"(y)); return d;
}
__device__ __forceinline__ float lo2(ULL v) {
    float x, y; asm("mov.b64 {%0, %1}, %2;" : "=f"(x), "=f"(y) : "l"(v)); return x;
}
__device__ __forceinline__ float hi2(ULL v) {
    float x, y; asm("mov.b64 {%0, %1}, %2;" : "=f"(x), "=f"(y) : "l"(v)); return y;
}

// ---------------- mma.sync / cp.async helpers ------------------------------
__device__ __forceinline__ uint32_t smem_u32(const void* p) {
    uint32_t a;
    asm("{ .reg .u64 t; cvta.to.shared.u64 t, %1; cvt.u32.u64 %0, t; }"
        : "=r"(a) : "l"(p));
    return a;
}
#define LDM4(r, addr) \
    asm volatile("ldmatrix.sync.aligned.m8n8.x4.shared.b16 {%0,%1,%2,%3}, [%4];" \
        : "=r"((r)[0]), "=r"((r)[1]), "=r"((r)[2]), "=r"((r)[3]) : "r"(addr))
#define MMA16816(c, a, b) \
    asm volatile("mma.sync.aligned.m16n8k16.row.col.f32.bf16.bf16.f32 " \
        "{%0,%1,%2,%3}, {%4,%5,%6,%7}, {%8,%9}, {%0,%1,%2,%3};" \
        : "+f"((c)[0]), "+f"((c)[1]), "+f"((c)[2]), "+f"((c)[3]) \
        : "r"((a)[0]), "r"((a)[1]), "r"((a)[2]), "r"((a)[3]), \
          "r"((b)[0]), "r"((b)[1]))
#define CP16(dst, src) \
    asm volatile("cp.async.ca.shared.global [%0], [%1], 16;" \
        :: "r"(dst), "l"(src))
#define CP_COMMIT() asm volatile("cp.async.commit_group;" ::: "memory")
#define CP_WAIT1()  asm volatile("cp.async.wait_group 1;" ::: "memory")
#define CP_WAIT0()  asm volatile("cp.async.wait_group 0;" ::: "memory")

// SMEM layout (bytes). Rows padded to 400B (200 bf16) -> conflict-free ldmatrix.
// A: 128 rows hi+lo. B ring: 2 buffers, each (hi 25600 + lo 25600).
#define ROWB 400
#define SA_HI 0
#define SA_LO 51200
#define S_B   102400
#define B_BUF 51200
#define SMEM_SZ 204800

__device__ __forceinline__ void split_store4p(char* hi, char* lo, float4 v) {
    __nv_bfloat16 h0 = __float2bfloat16(v.x);
    __nv_bfloat16 h1 = __float2bfloat16(v.y);
    __nv_bfloat16 h2 = __float2bfloat16(v.z);
    __nv_bfloat16 h3 = __float2bfloat16(v.w);
    __nv_bfloat16 l0 = __float2bfloat16(v.x - __bfloat162float(h0));
    __nv_bfloat16 l1 = __float2bfloat16(v.y - __bfloat162float(h1));
    __nv_bfloat16 l2 = __float2bfloat16(v.z - __bfloat162float(h2));
    __nv_bfloat16 l3 = __float2bfloat16(v.w - __bfloat162float(h3));
    reinterpret_cast<__nv_bfloat162*>(hi)[0] = __nv_bfloat162(h0, h1);
    reinterpret_cast<__nv_bfloat162*>(hi)[1] = __nv_bfloat162(h2, h3);
    reinterpret_cast<__nv_bfloat162*>(lo)[0] = __nv_bfloat162(l0, l1);
    reinterpret_cast<__nv_bfloat162*>(lo)[1] = __nv_bfloat162(l2, l3);
}

// Issue cp.async for one B slice (64 n-rows x 192 k bf16, hi+lo) into dstbase.
__device__ __forceinline__ void stage_b_async(
    uint32_t dstbase, const __nv_bfloat16* hi, const __nv_bfloat16* lo,
    int n0, int t)
{
#pragma unroll
    for (int plane = 0; plane < 2; plane++) {
        const __nv_bfloat16* src = plane ? lo : hi;
        const uint32_t dplane = dstbase + plane * 25600u;
#pragma unroll
        for (int c = 0; c < 6; c++) {
            const int chunk = c * 256 + t;          // 0..1535
            const int row = chunk / 24;
            const int ck  = chunk % 24;
            CP16(dplane + (uint32_t)row * ROWB + ck * 16,
                 src + ((size_t)(n0 + row)) * 192 + ck * 8);
        }
    }
}

// Per-warp 32x32 sub-tile of D(128x64): 3-term split-bf16 MMA from smem.
__device__ __forceinline__ void gemm_body(const uint32_t sbase, uint32_t bbase,
                                          int lane, int m_base, int n_base,
                                          float acc[2][4][4]) {
    const uint32_t aoff = (uint32_t)(m_base + (lane & 15)) * ROWB +
                          (uint32_t)(lane >> 4) * 16;
    const uint32_t a_hi = sbase + SA_HI + aoff;
    const uint32_t a_lo = sbase + SA_LO + aoff;
    const uint32_t boff =
        (uint32_t)(n_base + (lane & 7) + (((lane >> 4) & 1) << 3)) * ROWB +
        (uint32_t)((lane >> 3) & 1) * 16;
    const uint32_t b_hi = bbase + boff;
    const uint32_t b_lo = bbase + 25600u + boff;

#pragma unroll
    for (int ks = 0; ks < 12; ks++) {
        const uint32_t kb = ks * 32;
        uint32_t ah[2][4], al[2][4], bh[2][4], bl[2][4];
        LDM4(ah[0], a_hi + kb);
        LDM4(ah[1], a_hi + 16 * ROWB + kb);
        LDM4(al[0], a_lo + kb);
        LDM4(al[1], a_lo + 16 * ROWB + kb);
        LDM4(bh[0], b_hi + kb);
        LDM4(bh[1], b_hi + 16 * ROWB + kb);
        LDM4(bl[0], b_lo + kb);
        LDM4(bl[1], b_lo + 16 * ROWB + kb);
#pragma unroll
        for (int mi = 0; mi < 2; mi++) {
#pragma unroll
            for (int ni = 0; ni < 4; ni++) {
                uint32_t bfh[2] = {bh[ni >> 1][(ni & 1) * 2],
                                   bh[ni >> 1][(ni & 1) * 2 + 1]};
                uint32_t bfl[2] = {bl[ni >> 1][(ni & 1) * 2],
                                   bl[ni >> 1][(ni & 1) * 2 + 1]};
                MMA16816(acc[mi][ni], ah[mi], bfh);
                MMA16816(acc[mi][ni], al[mi], bfh);
                MMA16816(acc[mi][ni], ah[mi], bfl);
            }
        }
    }
}

// ---------------------------------------------------------------------------
// Kernel 0: weight pre-conversion into [n][k] bf16 hi/lo planes.
// ---------------------------------------------------------------------------
__global__ __launch_bounds__(256) void k_prep(
    const float* __restrict__ wq, const float* __restrict__ wl)
{
    const int idx = blockIdx.x * 256 + threadIdx.x;
    if (idx < 576 * 192) {
        const int n = idx / 192, k = idx - n * 192;
        const float v = wq[(size_t)k * 576 + n];
        const __nv_bfloat16 h = __float2bfloat16(v);
        g_wq_hi[idx] = h;
        g_wq_lo[idx] = __float2bfloat16(v - __bfloat162float(h));
    }
    if (idx < 192 * 192) {
        const int n = idx / 192, k = idx - n * 192;
        const float v = wl[(size_t)k * 192 + n];
        const __nv_bfloat16 h = __float2bfloat16(v);
        g_wl_hi[idx] = h;
        g_wl_lo[idx] = __float2bfloat16(v - __bfloat162float(h));
    }
}

// ---------------------------------------------------------------------------
// Kernel 1: QKV projection. Grid (2048), 256 threads. One block = one M-tile
// (2 windows); loops all 9 n-tiles with cp.async double-buffered B.
// ---------------------------------------------------------------------------
__global__ __launch_bounds__(256) void k_qkv(
    const float* __restrict__ x, const float* __restrict__ bias)
{
    extern __shared__ char sm[];
    const uint32_t sbase = smem_u32(sm);
    const int t    = threadIdx.x;
    const int lane = t & 31;
    const int wid  = t >> 5;
    const int mt   = blockIdx.x;

    // prefetch B(0) while we stage/convert A
    stage_b_async(sbase + S_B, g_wq_hi, g_wq_lo, 0, t);
    CP_COMMIT();

    // --- stage A (128 tokens x 192 ch), shift fused, split hi/lo
    for (int idx4 = t; idx4 < 6144; idx4 += 256) {
        const int m  = idx4 / 48;
        const int k4 = idx4 % 48;
        const int win = mt * 2 + (m >> 6);
        const int b  = win >> 10, wy = (win >> 5) & 31, wx = win & 31;
        const int p  = m & 63;
        const int shh = ((wy << 3) + (p >> 3) + 4) & 255;
        const int sww = ((wx << 3) + (p & 7) + 4) & 255;
        const float4 v = *reinterpret_cast<const float4*>(
            x + ((((size_t)b << 8) + shh) * 256 + sww) * 192 + k4 * 4);
        const uint32_t off = (uint32_t)m * ROWB + k4 * 8;
        split_store4p(sm + SA_HI + off, sm + SA_LO + off, v);
    }

    const int m_base = (wid >> 1) * 32;
    const int n_base = (wid & 1) * 32;
    const int lane4 = lane >> 2;
    const int lane2 = (lane & 3) * 2;

    for (int nt = 0; nt < 9; nt++) {
        __syncthreads();   // prev MMA done before overwriting the other buffer
        if (nt < 8) {
            stage_b_async(sbase + S_B + ((nt + 1) & 1) * B_BUF,
                          g_wq_hi, g_wq_lo, (nt + 1) * 64, t);
            CP_COMMIT();
            CP_WAIT1();    // B(nt) complete
        } else {
            CP_WAIT0();
        }
        __syncthreads();

        float acc[2][4][4] = {};
        gemm_body(sbase, sbase + S_B + (nt & 1) * B_BUF,
                  lane, m_base, n_base, acc);

        // epilogue: scatter into g_qkv [which][win*6+head][p][d]
        const int n0 = nt * 64;
#pragma unroll
        for (int mi = 0; mi < 2; mi++) {
            const int r  = m_base + mi * 16 + lane4;
            const int r2 = r + 8;
            const int win = mt * 2 + (r >> 6);
            const int p  = r & 63;
            const int p2 = r2 & 63;
#pragma unroll
            for (int ni = 0; ni < 4; ni++) {
                const int ng = n0 + n_base + ni * 8 + lane2;
                const int which = ng / 192;
                const int rr = ng - which * 192;
                const int head = rr >> 5;
                const int d = rr & 31;
                const float2 bb = *reinterpret_cast<const float2*>(bias + ng);
                float* gq = g_qkv + (size_t)which * QKV_STRIDE +
                            ((size_t)win * 6 + head) * 2048 + d;
                *reinterpret_cast<float2*>(gq + (size_t)p * 32) =
                    make_float2(acc[mi][ni][0] + bb.x, acc[mi][ni][1] + bb.y);
                *reinterpret_cast<float2*>(gq + (size_t)p2 * 32) =
                    make_float2(acc[mi][ni][2] + bb.x, acc[mi][ni][3] + bb.y);
            }
        }
    }
}

// ---------------------------------------------------------------------------
// Kernel 2: windowed attention (FFMA2). Grid (4096, 6), 64 threads.
// ---------------------------------------------------------------------------
__global__ __launch_bounds__(64) void k_attn(const float* __restrict__ rel_pos)
{
    const int win  = blockIdx.x;
    const int head = blockIdx.y;
    const int wy = (win >> 5) & 31;
    const int wx = win & 31;
    const int p  = threadIdx.x;

    __shared__ float Ks[64][32];
    __shared__ float Vs[64][32];

    const size_t base = ((size_t)win * 6 + head) * 2048;
    const float* qb = g_qkv + base;
    const float* kb = g_qkv + QKV_STRIDE + base;
    const float* vb = g_qkv + 2 * QKV_STRIDE + base;

    ULL q2[16];
#pragma unroll
    for (int u = 0; u < 8; u++) {
        const ulonglong2 qv =
            *reinterpret_cast<const ulonglong2*>(qb + p * 32 + u * 4);
        q2[2 * u] = qv.x; q2[2 * u + 1] = qv.y;
        *reinterpret_cast<float4*>(&Ks[p][u * 4]) =
            *reinterpret_cast<const float4*>(kb + p * 32 + u * 4);
        *reinterpret_cast<float4*>(&Vs[p][u * 4]) =
            *reinterpret_cast<const float4*>(vb + p * 32 + u * 4);
    }
    __syncthreads();

    const int y1 = p >> 3, x1 = p & 7;
    const bool lastR = (wy == 31);
    const bool lastC = (wx == 31);

    float sc[64];
    float mx = -1e30f;
#pragma unroll 4
    for (int j = 0; j < 64; j++) {
        ULL s2a = 0ull, s2b = 0ull;
        const ulonglong2* kp = reinterpret_cast<const ulonglong2*>(&Ks[j][0]);
#pragma unroll
        for (int u = 0; u < 8; u++) {
            const ulonglong2 kv = kp[u];
            s2a = fma2(q2[2 * u], kv.x, s2a);
            s2b = fma2(q2[2 * u + 1], kv.y, s2b);
        }
        float s = (lo2(s2a) + hi2(s2a)) + (lo2(s2b) + hi2(s2b));
        s *= 0.1767766953f;
        const int y2 = j >> 3, x2 = j & 7;
        s += rel_pos[((y1 - y2 + 7) * 15 + (x1 - x2 + 7)) * 6 + head];
        const bool bad = (lastR && ((y1 < 4) != (y2 < 4))) ||
                         (lastC && ((x1 < 4) != (x2 < 4)));
        if (bad) s = -1e30f;
        sc[j] = s;
        mx = fmaxf(mx, s);
    }
    float sum = 0.f;
#pragma unroll 4
    for (int j = 0; j < 64; j++) { sc[j] = __expf(sc[j] - mx); sum += sc[j]; }
    const float inv = 1.f / sum;

    ULL out2[16];
#pragma unroll
    for (int u = 0; u < 16; u++) out2[u] = 0ull;
#pragma unroll 4
    for (int j = 0; j < 64; j++) {
        const ULL wj = pack2(sc[j], sc[j]);
        const ulonglong2* vp = reinterpret_cast<const ulonglong2*>(&Vs[j][0]);
#pragma unroll
        for (int u = 0; u < 8; u++) {
            const ulonglong2 vv = vp[u];
            out2[2 * u]     = fma2(wj, vv.x, out2[2 * u]);
            out2[2 * u + 1] = fma2(wj, vv.y, out2[2 * u + 1]);
        }
    }

    float* ob = g_attn + ((size_t)win * 64 + p) * 192 + head * 32;
#pragma unroll
    for (int u = 0; u < 8; u++) {
        float4 st;
        st.x = lo2(out2[2 * u])     * inv;
        st.y = hi2(out2[2 * u])     * inv;
        st.z = lo2(out2[2 * u + 1]) * inv;
        st.w = hi2(out2[2 * u + 1]) * inv;
        *reinterpret_cast<float4*>(ob + u * 4) = st;
    }
}

// ---------------------------------------------------------------------------
// Kernel 3: output projection. Grid (2048), 256 threads, loops 3 n-tiles.
// ---------------------------------------------------------------------------
__global__ __launch_bounds__(256) void k_proj(
    const float* __restrict__ bias, float* __restrict__ out)
{
    extern __shared__ char sm[];
    const uint32_t sbase = smem_u32(sm);
    const int t    = threadIdx.x;
    const int lane = t & 31;
    const int wid  = t >> 5;
    const int mt   = blockIdx.x;

    stage_b_async(sbase + S_B, g_wl_hi, g_wl_lo, 0, t);
    CP_COMMIT();

    // --- stage A (contiguous 128x192 from g_attn)
    const float* abase = g_attn + (size_t)mt * 128 * 192;
    for (int idx4 = t; idx4 < 6144; idx4 += 256) {
        const int m  = idx4 / 48;
        const int k4 = idx4 % 48;
        const float4 v = *reinterpret_cast<const float4*>(abase + m * 192 + k4 * 4);
        const uint32_t off = (uint32_t)m * ROWB + k4 * 8;
        split_store4p(sm + SA_HI + off, sm + SA_LO + off, v);
    }

    const int m_base = (wid >> 1) * 32;
    const int n_base = (wid & 1) * 32;
    const int lane4 = lane >> 2;
    const int lane2 = (lane & 3) * 2;

    for (int nt = 0; nt < 3; nt++) {
        __syncthreads();
        if (nt < 2) {
            stage_b_async(sbase + S_B + ((nt + 1) & 1) * B_BUF,
                          g_wl_hi, g_wl_lo, (nt + 1) * 64, t);
            CP_COMMIT();
            CP_WAIT1();
        } else {
            CP_WAIT0();
        }
        __syncthreads();

        float acc[2][4][4] = {};
        gemm_body(sbase, sbase + S_B + (nt & 1) * B_BUF,
                  lane, m_base, n_base, acc);

        const int n0 = nt * 64;
#pragma unroll
        for (int mi = 0; mi < 2; mi++) {
#pragma unroll
            for (int half = 0; half < 2; half++) {
                const int r = m_base + mi * 16 + half * 8 + lane4;
                const int win = mt * 2 + (r >> 6);
                const int b  = win >> 10;
                const int wy = (win >> 5) & 31;
                const int wx = win & 31;
                const int p  = r & 63;
                const int oh = ((wy << 3) + (p >> 3) + 4) & 255;
                const int ow = ((wx << 3) + (p & 7) + 4) & 255;
                float* orow = out + ((((size_t)b << 8) + oh) * 256 + ow) * 192;
#pragma unroll
                for (int ni = 0; ni < 4; ni++) {
                    const int ng = n0 + n_base + ni * 8 + lane2;
                    const float2 bb = *reinterpret_cast<const float2*>(bias + ng);
                    float2 st;
                    st.x = acc[mi][ni][half * 2 + 0] + bb.x;
                    st.y = acc[mi][ni][half * 2 + 1] + bb.y;
                    *reinterpret_cast<float2*>(orow + ng) = st;
                }
            }
        }
    }
}

// ---------------------------------------------------------------------------
extern "C" void kernel_launch(void* const* d_in, const int* in_sizes, int n_in,
                              void* d_out, int out_size)
{
    const float* x     = (const float*)d_in[0];
    const float* w_qkv = (const float*)d_in[1];
    const float* b_qkv = (const float*)d_in[2];
    const float* w_lin = (const float*)d_in[3];
    const float* b_lin = (const float*)d_in[4];
    const float* rel   = (const float*)d_in[5];
    float* out = (float*)d_out;

    cudaFuncSetAttribute(k_qkv, cudaFuncAttributeMaxDynamicSharedMemorySize, SMEM_SZ);
    cudaFuncSetAttribute(k_proj, cudaFuncAttributeMaxDynamicSharedMemorySize, SMEM_SZ);

    k_prep<<<432, 256>>>(w_qkv, w_lin);
    k_qkv <<<2048, 256, SMEM_SZ>>>(x, b_qkv);
    k_attn<<<dim3(4096, 6), 64>>>(rel);
    k_proj<<<2048, 256, SMEM_SZ>>>(b_lin, out);
}